// round 2
// baseline (speedup 1.0000x reference)
#include <cuda_runtime.h>
#include <math.h>

#define B_   128
#define S_   1000
#define H_   256
#define M_   (B_ * S_)   // 128000

// ---------------- scratch (__device__ globals; no allocation allowed) ----------
__device__ float g_ce[B_ * H_];
__device__ float g_ct[B_ * H_];
__device__ float g_cs[B_ * H_];
__device__ float g_scores[2 * M_];        // [0]=enc, [1]=tgt (then softmaxed in place)
__device__ float g_ctx[2 * B_ * H_];      // enc ctx, tgt ctx
__device__ float g_d[2 * B_ * H_];        // d_e, d_t
__device__ float g_Tp[M_ * H_];           // raw Wp1 @ static, 131 MB

// ---------------- kernel 1: zero atomic accumulators --------------------------
__global__ void zero_kernel() {
    int i = blockIdx.x * blockDim.x + threadIdx.x;
    if (i < 2 * M_) g_scores[i] = 0.0f;
    if (i < 2 * B_ * H_) g_ctx[i] = 0.0f;
}

// ---------------- kernel 2: GRU step + per-batch bias vectors -----------------
__global__ void gru_kernel(const float* __restrict__ dec,
                           const float* __restrict__ lasth,
                           const float* __restrict__ tgt,
                           const float* __restrict__ semb,
                           const float* __restrict__ Wih,
                           const float* __restrict__ Whh,
                           const float* __restrict__ bih,
                           const float* __restrict__ bhh,
                           const float* __restrict__ Wenc,
                           const float* __restrict__ Wtgt,
                           const float* __restrict__ Wptr,
                           float* __restrict__ out_h) {
    int b = blockIdx.x, t = threadIdx.x;
    __shared__ float sx[H_], sh[H_], st[H_], ss[H_], shn[H_];
    sx[t] = dec[b * H_ + t];
    sh[t] = lasth[b * H_ + t];
    st[t] = tgt[b * H_ + t];
    ss[t] = semb[b * H_ + t];
    __syncthreads();

    float gir = bih[t], giz = bih[t + H_], gig = bih[t + 2 * H_];
    float ghr = bhh[t], ghz = bhh[t + H_], ghg = bhh[t + 2 * H_];
    const float* wi0 = Wih + t * H_;
    const float* wi1 = Wih + (t + H_) * H_;
    const float* wi2 = Wih + (t + 2 * H_) * H_;
    const float* wh0 = Whh + t * H_;
    const float* wh1 = Whh + (t + H_) * H_;
    const float* wh2 = Whh + (t + 2 * H_) * H_;
    #pragma unroll 4
    for (int k = 0; k < H_; ++k) {
        float x = sx[k], h = sh[k];
        gir += wi0[k] * x; giz += wi1[k] * x; gig += wi2[k] * x;
        ghr += wh0[k] * h; ghz += wh1[k] * h; ghg += wh2[k] * h;
    }
    float r = 1.0f / (1.0f + expf(-(gir + ghr)));
    float z = 1.0f / (1.0f + expf(-(giz + ghz)));
    float n = tanhf(gig + r * ghg);
    float hn = (1.0f - z) * n + z * sh[t];
    shn[t] = hn;
    out_h[b * H_ + t] = hn;   // last_hh_new output
    __syncthreads();

    // c_e = W_enc[:, H:2H] @ h_new ; c_t = W_tgt[:, H:2H] @ target ; c_s = W_ptr[:, 2H:3H] @ state
    float ce = 0.f, ct = 0.f, cs = 0.f;
    const float* we = Wenc + t * (2 * H_) + H_;
    const float* wt = Wtgt + t * (2 * H_) + H_;
    const float* wp = Wptr + t * (3 * H_) + 2 * H_;
    #pragma unroll 4
    for (int k = 0; k < H_; ++k) {
        ce += we[k] * shn[k];
        ct += wt[k] * st[k];
        cs += wp[k] * ss[k];
    }
    g_ce[b * H_ + t] = ce;
    g_ct[b * H_ + t] = ct;
    g_cs[b * H_ + t] = cs;
}

// ---------------- kernel 3: big fused GEMM -------------------------------------
// X (M,256) x Wcat^T (768,256). Tiles 64x64x32, 256 threads, 4x4 per thread.
// groups: 0 -> enc scores, 1 -> tgt scores, 2 -> store raw T_p.
__global__ void __launch_bounds__(256) gemm_fused(const float* __restrict__ X,
                                                  const float* __restrict__ Wenc,
                                                  const float* __restrict__ Wtgt,
                                                  const float* __restrict__ Wptr,
                                                  const float* __restrict__ v_enc,
                                                  const float* __restrict__ v_tgt) {
    __shared__ float As[32][64];
    __shared__ float Bs[32][64];
    __shared__ float red[64][17];

    const int tid = threadIdx.x;
    const int m0 = blockIdx.x * 64;
    const int nt = blockIdx.y;          // 0..11
    const int group = nt >> 2;
    const int n0 = (nt & 3) * 64;       // group-local column offset (0..192)

    const float* Wsrc;
    int stride;
    if (group == 0)      { Wsrc = Wenc; stride = 2 * H_; }
    else if (group == 1) { Wsrc = Wtgt; stride = 2 * H_; }
    else                 { Wsrc = Wptr; stride = 3 * H_; }

    const int lm = tid & 63;    // row within tile for loading
    const int lq = tid >> 6;    // 0..3 k-quad
    const int tn = tid & 15;    // 0..15
    const int tm = tid >> 4;    // 0..15

    float acc[4][4];
    #pragma unroll
    for (int i = 0; i < 4; ++i)
        #pragma unroll
        for (int j = 0; j < 4; ++j) acc[i][j] = 0.f;

    const float* xrow = X + (size_t)(m0 + lm) * H_;
    const float* wrow = Wsrc + (size_t)(n0 + lm) * stride;  // cols [0,H) of W

    for (int kt = 0; kt < 8; ++kt) {
        const int k0 = kt * 32;
        #pragma unroll
        for (int h = 0; h < 2; ++h) {
            const int kk = (lq + h * 4) * 4;   // 0,4,...,28
            float4 xa = *(const float4*)(xrow + k0 + kk);
            As[kk + 0][lm] = xa.x; As[kk + 1][lm] = xa.y;
            As[kk + 2][lm] = xa.z; As[kk + 3][lm] = xa.w;
            float4 wa = *(const float4*)(wrow + k0 + kk);
            Bs[kk + 0][lm] = wa.x; Bs[kk + 1][lm] = wa.y;
            Bs[kk + 2][lm] = wa.z; Bs[kk + 3][lm] = wa.w;
        }
        __syncthreads();
        #pragma unroll
        for (int k = 0; k < 32; ++k) {
            float4 a = *(const float4*)&As[k][tm * 4];
            float4 b = *(const float4*)&Bs[k][tn * 4];
            acc[0][0] += a.x * b.x; acc[0][1] += a.x * b.y; acc[0][2] += a.x * b.z; acc[0][3] += a.x * b.w;
            acc[1][0] += a.y * b.x; acc[1][1] += a.y * b.y; acc[1][2] += a.y * b.z; acc[1][3] += a.y * b.w;
            acc[2][0] += a.z * b.x; acc[2][1] += a.z * b.y; acc[2][2] += a.z * b.z; acc[2][3] += a.z * b.w;
            acc[3][0] += a.w * b.x; acc[3][1] += a.w * b.y; acc[3][2] += a.w * b.z; acc[3][3] += a.w * b.w;
        }
        __syncthreads();
    }

    if (group < 2) {
        const float* v = (group == 0) ? v_enc : v_tgt;
        const float* c = (group == 0) ? g_ce : g_ct;
        float* sc = g_scores + group * M_;
        #pragma unroll
        for (int i = 0; i < 4; ++i) {
            const int mg = m0 + tm * 4 + i;
            const int b = mg / S_;
            float p = 0.f;
            #pragma unroll
            for (int j = 0; j < 4; ++j) {
                const int n = n0 + tn * 4 + j;
                p += v[n] * tanhf(acc[i][j] + c[b * H_ + n]);
            }
            red[tm * 4 + i][tn] = p;
        }
        __syncthreads();
        if (tid < 64) {
            float s = 0.f;
            #pragma unroll
            for (int t = 0; t < 16; ++t) s += red[tid][t];
            atomicAdd(sc + m0 + tid, s);
        }
    } else {
        #pragma unroll
        for (int i = 0; i < 4; ++i) {
            const int mg = m0 + tm * 4 + i;
            float4 o = make_float4(acc[i][0], acc[i][1], acc[i][2], acc[i][3]);
            *(float4*)(g_Tp + (size_t)mg * H_ + n0 + tn * 4) = o;
        }
    }
}

// ---------------- kernel 4: softmax over S (in place) --------------------------
__global__ void softmax_kernel() {
    const int b = blockIdx.x, which = blockIdx.y;
    float* s = g_scores + which * M_ + b * S_;
    const int t = threadIdx.x;
    __shared__ float sred[9];

    float mx = -1e30f;
    for (int i = t; i < S_; i += 256) mx = fmaxf(mx, s[i]);
    #pragma unroll
    for (int o = 16; o > 0; o >>= 1) mx = fmaxf(mx, __shfl_xor_sync(0xffffffffu, mx, o));
    if ((t & 31) == 0) sred[t >> 5] = mx;
    __syncthreads();
    if (t == 0) {
        float m = sred[0];
        for (int w = 1; w < 8; ++w) m = fmaxf(m, sred[w]);
        sred[8] = m;
    }
    __syncthreads();
    mx = sred[8];

    float sm = 0.f;
    for (int i = t; i < S_; i += 256) sm += expf(s[i] - mx);
    #pragma unroll
    for (int o = 16; o > 0; o >>= 1) sm += __shfl_xor_sync(0xffffffffu, sm, o);
    if ((t & 31) == 0) sred[t >> 5] = sm;
    __syncthreads();
    if (t == 0) {
        float m = 0.f;
        for (int w = 0; w < 8; ++w) m += sred[w];
        sred[8] = 1.0f / m;
    }
    __syncthreads();
    const float inv = sred[8];
    for (int i = t; i < S_; i += 256) s[i] = expf(s[i] - mx) * inv;
}

// ---------------- kernel 5: attention-weighted contexts ------------------------
__global__ void context_kernel(const float* __restrict__ X) {
    const int b = blockIdx.x, chunk = blockIdx.y;  // 10 chunks of 100
    const int t = threadIdx.x;                     // h index
    const float* ae = g_scores + b * S_ + chunk * 100;
    const float* at = g_scores + M_ + b * S_ + chunk * 100;
    const float* x = X + ((size_t)b * S_ + chunk * 100) * H_ + t;
    float ce = 0.f, ct = 0.f;
    #pragma unroll 4
    for (int s = 0; s < 100; ++s) {
        const float xv = x[(size_t)s * H_];
        ce += ae[s] * xv;
        ct += at[s] * xv;
    }
    atomicAdd(&g_ctx[b * H_ + t], ce);
    atomicAdd(&g_ctx[B_ * H_ + b * H_ + t], ct);
}

// ---------------- kernel 6: d vectors ------------------------------------------
__global__ void dvec_kernel(const float* __restrict__ Wptr) {
    const int b = blockIdx.x, t = threadIdx.x;
    __shared__ float se[H_], stt[H_];
    se[t] = g_ctx[b * H_ + t];
    stt[t] = g_ctx[B_ * H_ + b * H_ + t];
    __syncthreads();
    float de = g_cs[b * H_ + t], dt = de;
    const float* wr = Wptr + t * (3 * H_) + H_;   // cols [H, 2H)
    #pragma unroll 4
    for (int k = 0; k < H_; ++k) {
        const float w = wr[k];
        de += w * se[k];
        dt += w * stt[k];
    }
    g_d[b * H_ + t] = de;
    g_d[B_ * H_ + b * H_ + t] = dt;
}

// ---------------- kernel 7: final probs ----------------------------------------
__global__ void final_kernel(const float* __restrict__ v_ptr, float* __restrict__ out) {
    const int m = blockIdx.x * 8 + (threadIdx.x >> 5);
    const int lane = threadIdx.x & 31;
    const int b = m / S_;
    const float* tp = g_Tp + (size_t)m * H_;
    const float* de = g_d + b * H_;
    const float* dt = g_d + B_ * H_ + b * H_;
    float pe = 0.f, pt = 0.f;
    #pragma unroll
    for (int h0 = 0; h0 < H_; h0 += 32) {
        const int h = h0 + lane;
        const float tv = tp[h];
        const float vv = v_ptr[h];
        pe += vv * tanhf(tv + de[h]);
        pt += vv * tanhf(tv + dt[h]);
    }
    #pragma unroll
    for (int o = 16; o > 0; o >>= 1) {
        pe += __shfl_xor_sync(0xffffffffu, pe, o);
        pt += __shfl_xor_sync(0xffffffffu, pt, o);
    }
    if (lane == 0) out[m] = 5.0f * pe + pt;
}

// ---------------- launch ---------------------------------------------------------
extern "C" void kernel_launch(void* const* d_in, const int* in_sizes, int n_in,
                              void* d_out, int out_size) {
    const float* x_static = (const float*)d_in[0];
    const float* state_emb = (const float*)d_in[1];
    const float* dec = (const float*)d_in[2];
    const float* tgt = (const float*)d_in[3];
    const float* lasth = (const float*)d_in[4];
    const float* Wih = (const float*)d_in[5];
    const float* Whh = (const float*)d_in[6];
    const float* bih = (const float*)d_in[7];
    const float* bhh = (const float*)d_in[8];
    const float* v_enc = (const float*)d_in[9];
    const float* Wenc = (const float*)d_in[10];
    const float* v_tgt = (const float*)d_in[11];
    const float* Wtgt = (const float*)d_in[12];
    const float* v_ptr = (const float*)d_in[13];
    const float* Wptr = (const float*)d_in[14];

    float* out_probs = (float*)d_out;            // B*S
    float* out_h = (float*)d_out + M_;           // 1*B*H

    zero_kernel<<<(2 * M_ + 255) / 256, 256>>>();
    gru_kernel<<<B_, H_>>>(dec, lasth, tgt, state_emb, Wih, Whh, bih, bhh,
                           Wenc, Wtgt, Wptr, out_h);
    gemm_fused<<<dim3(M_ / 64, 12), 256>>>(x_static, Wenc, Wtgt, Wptr, v_enc, v_tgt);
    softmax_kernel<<<dim3(B_, 2), 256>>>();
    context_kernel<<<dim3(B_, 10), H_>>>(x_static);
    dvec_kernel<<<B_, H_>>>(Wptr);
    final_kernel<<<M_ / 8, 256>>>(v_ptr, out_probs);
}